// round 16
// baseline (speedup 1.0000x reference)
#include <cuda_runtime.h>
#include <cuda_bf16.h>
#include <math.h>
#include <stdint.h>

#define NN 1024
#define BB 128
#define NT 256
#define DT 0.1f
#define STEPS 10

#define TM 64
#define TN 32
#define BK 64
#define NCH 16
#define GRID 128          // 16 i-tiles x 8 n-tile groups, all co-resident
#define THREADS 512       // 16 warps: 4 m-warps x 2 n-warps x 2 k-groups

#define SA_BYTES (NCH * TM * BK)      /* 64 KB resident fp8 A tile */
#define SB_STAGE (TN * BK)            /* 2 KB per chunk (fp8) */
#define SB_BYTES (NCH * SB_STAGE)     /* 32 KB fp8 B panel */
#define RED_OFF  SA_BYTES             /* 8 KB k-group reduction (reuses B region) */
#define EP_OFF   (SA_BYTES + 8192)    /* 2 KB fp8 staging (reuses B region) */
#define SM_TOTAL (SA_BYTES + SB_BYTES + 512)

// ---------------- device scratch ----------------------------------------
__device__ uint8_t  g_scB[2][NT * NN];   // ping-pong fp8 B operand [n][j]
__device__ float    g_redS[BB];
__device__ float    g_redC[BB];
__device__ unsigned g_gcnt[8];
__device__ unsigned g_ggen[8];

// ---------------- PTX helpers --------------------------------------------
__device__ __forceinline__ uint32_t smem_u32(const void* p) {
    uint32_t a;
    asm("{ .reg .u64 t; cvta.to.shared.u64 t, %1; cvt.u32.u64 %0, t; }" : "=r"(a) : "l"(p));
    return a;
}
__device__ __forceinline__ void cp16(uint32_t dst, const void* src) {
    asm volatile("cp.async.cg.shared.global [%0], [%1], 16;" :: "r"(dst), "l"(src));
}
#define CP_COMMIT() asm volatile("cp.async.commit_group;" ::: "memory")

__device__ __forceinline__ void ldm4(uint32_t& r0, uint32_t& r1, uint32_t& r2, uint32_t& r3,
                                     uint32_t addr) {
    asm volatile("ldmatrix.sync.aligned.m8n8.x4.shared.b16 {%0,%1,%2,%3}, [%4];"
                 : "=r"(r0), "=r"(r1), "=r"(r2), "=r"(r3) : "r"(addr));
}
__device__ __forceinline__ void mma_fp8(float* d, const uint32_t* a, uint32_t b0, uint32_t b1) {
    asm volatile(
        "mma.sync.aligned.m16n8k32.row.col.f32.e4m3.e4m3.f32 "
        "{%0,%1,%2,%3}, {%4,%5,%6,%7}, {%8,%9}, {%0,%1,%2,%3};"
        : "+f"(d[0]), "+f"(d[1]), "+f"(d[2]), "+f"(d[3])
        : "r"(a[0]), "r"(a[1]), "r"(a[2]), "r"(a[3]), "r"(b0), "r"(b1));
}
__device__ __forceinline__ uint32_t pack4_e4m3(float f0, float f1, float f2, float f3) {
    uint16_t lo, hi;
    asm("cvt.rn.satfinite.e4m3x2.f32 %0, %1, %2;" : "=h"(lo) : "f"(f1), "f"(f0));
    asm("cvt.rn.satfinite.e4m3x2.f32 %0, %1, %2;" : "=h"(hi) : "f"(f3), "f"(f2));
    return (uint32_t)lo | ((uint32_t)hi << 16);
}

// group barrier: 16 CTAs sharing nt
__device__ __forceinline__ void group_bar(int nt, unsigned& gen) {
    __syncthreads();
    if (threadIdx.x == 0) {
        unsigned prev;
        asm volatile("atom.release.gpu.add.u32 %0, [%1], %2;"
                     : "=r"(prev) : "l"(&g_gcnt[nt]), "r"(1u) : "memory");
        if (prev == 15u) {
            asm volatile("st.relaxed.gpu.u32 [%0], %1;" :: "l"(&g_gcnt[nt]), "r"(0u) : "memory");
            asm volatile("red.release.gpu.add.u32 [%0], %1;" :: "l"(&g_ggen[nt]), "r"(1u) : "memory");
        } else {
            unsigned v;
            do {
                asm volatile("ld.acquire.gpu.u32 %0, [%1];" : "=r"(v) : "l"(&g_ggen[nt]) : "memory");
            } while (v == gen);
        }
    }
    gen += 1;
    __syncthreads();
}

// ---------------------------------------------------------------------------
__global__ void zero_kernel() {
    int t = threadIdx.x;
    if (t < BB) { g_redS[t] = 0.f; g_redC[t] = 0.f; }
    if (t < 8) { g_gcnt[t] = 0u; g_ggen[t] = 0u; }
}

// ---------------------------------------------------------------------------
__global__ __launch_bounds__(THREADS, 1) void kuramoto_kernel(
    const float* __restrict__ theta_init,
    const float* __restrict__ Kmat,
    const float* __restrict__ omega,
    const float* __restrict__ Kg,
    float* __restrict__ out)
{
    extern __shared__ char smem[];
    const uint32_t sAu = smem_u32(smem);
    const uint32_t sBu = sAu + SA_BYTES;
    float* const  sRed = reinterpret_cast<float*>(smem + RED_OFF);   // [64 rows][32 cols]
    uint8_t* const sEp = reinterpret_cast<uint8_t*>(smem) + EP_OFF;  // [32 rows][64 cols]

    const int t = threadIdx.x;
    const int lane = t & 31;
    const int wid = t >> 5;
    const int wm = wid & 3;                 // 0..3
    const int wn = (wid >> 2) & 1;          // 0..1
    const int wk = wid >> 3;                // k-group 0/1
    const int it = blockIdx.x & 15;
    const int nt = blockIdx.x >> 4;
    const int i0 = it * TM;
    const int n0 = nt * TN;

    unsigned gen = 0;

    // ---------------- init: A tile f32 -> e4m3, swizzled, SMEM-resident ----
    #pragma unroll 4
    for (int u = t; u < NCH * TM * 4; u += THREADS) {    // 4096 16B units
        int k = u >> 8;
        int rem = u & 255;
        int r = rem >> 2;
        int un = rem & 3;
        const float* src = Kmat + (size_t)(i0 + r) * NN + k * 64 + un * 16;
        float4 v0 = *reinterpret_cast<const float4*>(src);
        float4 v1 = *reinterpret_cast<const float4*>(src + 4);
        float4 v2 = *reinterpret_cast<const float4*>(src + 8);
        float4 v3 = *reinterpret_cast<const float4*>(src + 12);
        uint4 w;
        w.x = pack4_e4m3(v0.x, v0.y, v0.z, v0.w);
        w.y = pack4_e4m3(v1.x, v1.y, v1.z, v1.w);
        w.z = pack4_e4m3(v2.x, v2.y, v2.z, v2.w);
        w.w = pack4_e4m3(v3.x, v3.y, v3.z, v3.w);
        *reinterpret_cast<uint4*>(smem + k * 4096 + r * 64 + ((un ^ ((r >> 1) & 3)) << 4)) = w;
    }

    // ---------------- per-thread indices / state (state owned by wk==0) ----
    const int tq = lane >> 2, tr = lane & 3;
    const int sub = lane >> 3, lr = lane & 7;
    float th[2][2], sr[2][2], cr[2][2];
    float om[2];
    int ig[2], bg[2], il[2], bl[2];
    #pragma unroll
    for (int half = 0; half < 2; half++) {
        il[half] = wm * 16 + half * 8 + tq;
        ig[half] = i0 + il[half];
        om[half] = omega[ig[half]];
    }
    #pragma unroll
    for (int nb = 0; nb < 2; nb++) {
        bl[nb] = wn * 8 + nb * 4 + tr;      // 0..15
        bg[nb] = nt * 16 + bl[nb];
    }

    const float kgn = Kg[0] * (1.0f / (float)NN);

    if (wk == 0) {
        #pragma unroll
        for (int nb = 0; nb < 2; nb++)
            #pragma unroll
            for (int half = 0; half < 2; half++) {
                float tv = theta_init[bg[nb] * NN + ig[half]];
                th[nb][half] = tv;
                float s, c;
                sincosf(tv, &s, &c);
                sr[nb][half] = s;
                cr[nb][half] = c;
            }
    }

    // publish step-0 B operand via staging + coalesced stores
    __syncthreads();
    if (wk == 0) {
        #pragma unroll
        for (int nb = 0; nb < 2; nb++)
            #pragma unroll
            for (int half = 0; half < 2; half++) {
                uint16_t pr;
                asm("cvt.rn.satfinite.e4m3x2.f32 %0, %1, %2;"
                    : "=h"(pr) : "f"(cr[nb][half]), "f"(sr[nb][half]));
                sEp[(2 * bl[nb]) * 64 + il[half]]     = (uint8_t)(pr & 0xFF);
                sEp[(2 * bl[nb] + 1) * 64 + il[half]] = (uint8_t)(pr >> 8);
            }
    }
    __syncthreads();
    if (t < 128) {
        int row = t >> 2, un = t & 3;
        *reinterpret_cast<uint4*>(&g_scB[0][(size_t)(n0 + row) * NN + i0 + un * 16]) =
            *reinterpret_cast<const uint4*>(sEp + row * 64 + un * 16);
    }

    group_bar(nt, gen);

    // ---------------- ldmatrix addressing ----------------------------------
    const int arow = wm * 16 + ((sub & 1) << 3) + lr;
    const int acsel = sub >> 1;
    const int asw = (arow >> 1) & 3;
    const uint32_t aBase = sAu + (uint32_t)(arow * 64);

    const int brow = wn * 16 + ((sub >> 1) << 3) + lr;
    const int bcsel = sub & 1;
    const int bsw = (brow >> 1) & 3;
    const uint32_t bBase = sBu + (uint32_t)(brow * 64);

    // ---------------- 10 steps ---------------------------------------------
    for (int s = 0; s < STEPS; s++) {
        const uint8_t* __restrict__ bsrc_t = g_scB[s & 1];
        uint8_t* __restrict__ Bdst = g_scB[(s + 1) & 1];

        // acc[chunk-parity][k2][nb][frag]: 8 independent chains per warp
        float acc[2][2][2][4];
        #pragma unroll
        for (int cp = 0; cp < 2; cp++)
            #pragma unroll
            for (int k2 = 0; k2 < 2; k2++)
                #pragma unroll
                for (int nb = 0; nb < 2; nb++)
                    #pragma unroll
                    for (int f = 0; f < 4; f++) acc[cp][k2][nb][f] = 0.f;

        // issue whole 32KB fp8 B panel: 4 quarter-commits, 1 cp16/thread each
        #pragma unroll
        for (int q = 0; q < 4; q++) {
            int u = q * 512 + t;
            int ck = u >> 7;
            int rem = u & 127;
            int row = rem >> 2;
            int un = rem & 3;
            uint32_t dst = sBu + (uint32_t)(ck * SB_STAGE + row * 64 +
                                            ((un ^ ((row >> 1) & 3)) << 4));
            cp16(dst, bsrc_t + (size_t)(n0 + row) * NN + ck * 64 + un * 16);
            CP_COMMIT();
        }

        // quarter Q: k-group wk computes chunks Q*4 + wk*2 + {0,1}
        #define QUARTER(Q, WG)                                                          \
        {                                                                               \
            asm volatile("cp.async.wait_group " #WG ";" ::: "memory");                  \
            __syncthreads();                                                            \
            _Pragma("unroll")                                                           \
            for (int cc = 0; cc < 2; cc++) {                                            \
                const int kk = (Q) * 4 + wk * 2 + cc;                                   \
                const uint32_t aC = aBase + (uint32_t)(kk * 4096);                      \
                const uint32_t bC = bBase + (uint32_t)(kk * SB_STAGE);                  \
                _Pragma("unroll")                                                       \
                for (int k2 = 0; k2 < 2; k2++) {                                        \
                    uint32_t a[4], b[4];                                                \
                    ldm4(a[0], a[1], a[2], a[3],                                        \
                         aC + (uint32_t)(((2 * k2 + acsel) ^ asw) << 4));               \
                    ldm4(b[0], b[1], b[2], b[3],                                        \
                         bC + (uint32_t)(((2 * k2 + bcsel) ^ bsw) << 4));               \
                    mma_fp8(acc[cc][k2][0], a, b[0], b[1]);                             \
                    mma_fp8(acc[cc][k2][1], a, b[2], b[3]);                             \
                }                                                                       \
            }                                                                           \
        }
        QUARTER(0, 3)
        QUARTER(1, 2)
        QUARTER(2, 1)
        QUARTER(3, 0)
        #undef QUARTER

        // ---- epilogue: merge k-groups via smem, Euler in wk==0 -------------
        __syncthreads();   // all sB reads done; B region reusable
        if (wk == 1) {
            #pragma unroll
            for (int nb = 0; nb < 2; nb++)
                #pragma unroll
                for (int half = 0; half < 2; half++) {
                    float S = (acc[0][0][nb][half * 2] + acc[0][1][nb][half * 2]) +
                              (acc[1][0][nb][half * 2] + acc[1][1][nb][half * 2]);
                    float C = (acc[0][0][nb][half * 2 + 1] + acc[0][1][nb][half * 2 + 1]) +
                              (acc[1][0][nb][half * 2 + 1] + acc[1][1][nb][half * 2 + 1]);
                    *reinterpret_cast<float2*>(
                        &sRed[il[half] * 32 + wn * 16 + nb * 8 + tr * 2]) =
                        make_float2(S, C);
                }
        }
        __syncthreads();
        if (wk == 0) {
            #pragma unroll
            for (int nb = 0; nb < 2; nb++) {
                #pragma unroll
                for (int half = 0; half < 2; half++) {
                    float2 other = *reinterpret_cast<const float2*>(
                        &sRed[il[half] * 32 + wn * 16 + nb * 8 + tr * 2]);
                    float S = (acc[0][0][nb][half * 2] + acc[0][1][nb][half * 2]) +
                              (acc[1][0][nb][half * 2] + acc[1][1][nb][half * 2]) + other.x;
                    float C = (acc[0][0][nb][half * 2 + 1] + acc[0][1][nb][half * 2 + 1]) +
                              (acc[1][0][nb][half * 2 + 1] + acc[1][1][nb][half * 2 + 1]) + other.y;
                    float coup = cr[nb][half] * S - sr[nb][half] * C;
                    float tn = th[nb][half] + DT * (om[half] + kgn * coup);
                    th[nb][half] = tn;
                    float sv, cv;
                    sincosf(tn, &sv, &cv);
                    sr[nb][half] = sv;
                    cr[nb][half] = cv;
                    uint16_t pr;
                    asm("cvt.rn.satfinite.e4m3x2.f32 %0, %1, %2;"
                        : "=h"(pr) : "f"(cv), "f"(sv));
                    sEp[(2 * bl[nb]) * 64 + il[half]]     = (uint8_t)(pr & 0xFF);
                    sEp[(2 * bl[nb] + 1) * 64 + il[half]] = (uint8_t)(pr >> 8);
                }
            }
        }
        __syncthreads();
        if (t >= 256 && t < 384) {          // wk==1 warps do the global copy
            int r2 = t - 256;
            int row = r2 >> 2, un = r2 & 3;
            *reinterpret_cast<uint4*>(&Bdst[(size_t)(n0 + row) * NN + i0 + un * 16]) =
                *reinterpret_cast<const uint4*>(sEp + row * 64 + un * 16);
        }
        if (s != STEPS - 1) group_bar(nt, gen);
    }

    // ---------------- finalize (group-local) --------------------------------
    float* redS = reinterpret_cast<float*>(smem + SA_BYTES + SB_BYTES);
    float* redC = redS + 16;
    __syncthreads();
    if (t < 16) { redS[t] = 0.f; redC[t] = 0.f; }
    __syncthreads();

    if (wk == 0) {
        #pragma unroll
        for (int nb = 0; nb < 2; nb++) {
            atomicAdd(&redS[bl[nb]], sr[nb][0] + sr[nb][1]);
            atomicAdd(&redC[bl[nb]], cr[nb][0] + cr[nb][1]);
            #pragma unroll
            for (int half = 0; half < 2; half++)
                out[(size_t)bg[nb] * NN + ig[half]] = atan2f(sr[nb][half], cr[nb][half]);
        }
    }
    __syncthreads();
    if (t < 16) {
        atomicAdd(&g_redS[nt * 16 + t], redS[t]);
        atomicAdd(&g_redC[nt * 16 + t], redC[t]);
    }
    group_bar(nt, gen);

    if (it == 0 && t < 16) {
        int b = nt * 16 + t;
        float sm = g_redS[b] * (1.0f / (float)NN);
        float cm = g_redC[b] * (1.0f / (float)NN);
        out[(size_t)BB * NN + b] = sqrtf(cm * cm + sm * sm);
    }
}

// ---------------------------------------------------------------------------
extern "C" void kernel_launch(void* const* d_in, const int* in_sizes, int n_in,
                              void* d_out, int out_size) {
    const float* theta_init = (const float*)d_in[0];
    const float* Kmat       = (const float*)d_in[1];
    const float* omega      = (const float*)d_in[2];
    const float* Kg         = (const float*)d_in[3];
    float* out = (float*)d_out;

    cudaFuncSetAttribute(kuramoto_kernel,
                         cudaFuncAttributeMaxDynamicSharedMemorySize, SM_TOTAL);
    zero_kernel<<<1, 128>>>();
    kuramoto_kernel<<<GRID, THREADS, SM_TOTAL>>>(theta_init, Kmat, omega, Kg, out);
}

// round 17
// speedup vs baseline: 1.1276x; 1.1276x over previous
#include <cuda_runtime.h>
#include <cuda_bf16.h>
#include <math.h>
#include <stdint.h>

#define NN 1024
#define BB 128
#define NT 256
#define DT 0.1f
#define STEPS 10

#define TM 64
#define TN 32
#define BK 64
#define NCH 16
#define GRID 128          // 16 i-tiles x 8 n-tile groups, all co-resident
#define THREADS 256       // 8 warps: 4 m-warps x 2 n-warps, warp tile m16n16

#define SA_BYTES (NCH * TM * BK)      /* 64 KB resident fp8 A tile */
#define SB_STAGE (TN * BK)            /* 2 KB per chunk (fp8) */
#define SB_BYTES (NCH * SB_STAGE)     /* 32 KB: whole fp8 B panel per step */
#define SM_TOTAL (SA_BYTES + SB_BYTES + 512)

// ---------------- device scratch ----------------------------------------
__device__ uint8_t  g_scB[2][NT * NN];   // ping-pong fp8 B operand [n][j]
__device__ float    g_redS[BB];
__device__ float    g_redC[BB];
__device__ unsigned g_gcnt[8];
__device__ unsigned g_ggen[8];

// ---------------- PTX helpers --------------------------------------------
__device__ __forceinline__ uint32_t smem_u32(const void* p) {
    uint32_t a;
    asm("{ .reg .u64 t; cvta.to.shared.u64 t, %1; cvt.u32.u64 %0, t; }" : "=r"(a) : "l"(p));
    return a;
}
__device__ __forceinline__ void cp16(uint32_t dst, const void* src) {
    asm volatile("cp.async.cg.shared.global [%0], [%1], 16;" :: "r"(dst), "l"(src));
}
#define CP_COMMIT() asm volatile("cp.async.commit_group;" ::: "memory")

__device__ __forceinline__ void ldm4(uint32_t& r0, uint32_t& r1, uint32_t& r2, uint32_t& r3,
                                     uint32_t addr) {
    asm volatile("ldmatrix.sync.aligned.m8n8.x4.shared.b16 {%0,%1,%2,%3}, [%4];"
                 : "=r"(r0), "=r"(r1), "=r"(r2), "=r"(r3) : "r"(addr));
}
// fp8 e4m3 MMA, f32 accumulate, m16n8k32
__device__ __forceinline__ void mma_fp8(float* d, const uint32_t* a, uint32_t b0, uint32_t b1) {
    asm volatile(
        "mma.sync.aligned.m16n8k32.row.col.f32.e4m3.e4m3.f32 "
        "{%0,%1,%2,%3}, {%4,%5,%6,%7}, {%8,%9}, {%0,%1,%2,%3};"
        : "+f"(d[0]), "+f"(d[1]), "+f"(d[2]), "+f"(d[3])
        : "r"(a[0]), "r"(a[1]), "r"(a[2]), "r"(a[3]), "r"(b0), "r"(b1));
}
// pack 4 floats -> 4 e4m3 bytes (little-endian f0..f3)
__device__ __forceinline__ uint32_t pack4_e4m3(float f0, float f1, float f2, float f3) {
    uint16_t lo, hi;
    asm("cvt.rn.satfinite.e4m3x2.f32 %0, %1, %2;" : "=h"(lo) : "f"(f1), "f"(f0));
    asm("cvt.rn.satfinite.e4m3x2.f32 %0, %1, %2;" : "=h"(hi) : "f"(f3), "f"(f2));
    return (uint32_t)lo | ((uint32_t)hi << 16);
}

// group barrier: 16 CTAs sharing nt
__device__ __forceinline__ void group_bar(int nt, unsigned& gen) {
    __syncthreads();
    if (threadIdx.x == 0) {
        unsigned prev;
        asm volatile("atom.release.gpu.add.u32 %0, [%1], %2;"
                     : "=r"(prev) : "l"(&g_gcnt[nt]), "r"(1u) : "memory");
        if (prev == 15u) {
            asm volatile("st.relaxed.gpu.u32 [%0], %1;" :: "l"(&g_gcnt[nt]), "r"(0u) : "memory");
            asm volatile("red.release.gpu.add.u32 [%0], %1;" :: "l"(&g_ggen[nt]), "r"(1u) : "memory");
        } else {
            unsigned v;
            do {
                asm volatile("ld.acquire.gpu.u32 %0, [%1];" : "=r"(v) : "l"(&g_ggen[nt]) : "memory");
            } while (v == gen);
        }
    }
    gen += 1;
    __syncthreads();
}

// ---------------------------------------------------------------------------
__global__ void zero_kernel() {
    int t = threadIdx.x;
    if (t < BB) { g_redS[t] = 0.f; g_redC[t] = 0.f; }
    if (t < 8) { g_gcnt[t] = 0u; g_ggen[t] = 0u; }
}

// ---------------------------------------------------------------------------
__global__ __launch_bounds__(THREADS, 1) void kuramoto_kernel(
    const float* __restrict__ theta_init,
    const float* __restrict__ Kmat,
    const float* __restrict__ omega,
    const float* __restrict__ Kg,
    float* __restrict__ out)
{
    extern __shared__ char smem[];
    const uint32_t sAu = smem_u32(smem);
    const uint32_t sBu = sAu + SA_BYTES;
    uint8_t* const sEp = reinterpret_cast<uint8_t*>(smem) + SA_BYTES;  // staging (reuses B region)

    const int t = threadIdx.x;
    const int lane = t & 31;
    const int wid = t >> 5;
    const int wm = wid & 3;
    const int wn = wid >> 2;
    const int it = blockIdx.x & 15;
    const int nt = blockIdx.x >> 4;
    const int i0 = it * TM;
    const int n0 = nt * TN;

    unsigned gen = 0;

    // ---------------- init: A tile f32 -> e4m3, swizzled, SMEM-resident ----
    #pragma unroll 4
    for (int u = t; u < NCH * TM * 4; u += THREADS) {    // 4096 16B units
        int k = u >> 8;
        int rem = u & 255;
        int r = rem >> 2;
        int un = rem & 3;
        const float* src = Kmat + (size_t)(i0 + r) * NN + k * 64 + un * 16;
        float4 v0 = *reinterpret_cast<const float4*>(src);
        float4 v1 = *reinterpret_cast<const float4*>(src + 4);
        float4 v2 = *reinterpret_cast<const float4*>(src + 8);
        float4 v3 = *reinterpret_cast<const float4*>(src + 12);
        uint4 w;
        w.x = pack4_e4m3(v0.x, v0.y, v0.z, v0.w);
        w.y = pack4_e4m3(v1.x, v1.y, v1.z, v1.w);
        w.z = pack4_e4m3(v2.x, v2.y, v2.z, v2.w);
        w.w = pack4_e4m3(v3.x, v3.y, v3.z, v3.w);
        *reinterpret_cast<uint4*>(smem + k * 4096 + r * 64 + ((un ^ ((r >> 1) & 3)) << 4)) = w;
    }

    // ---------------- init: per-thread register state ----------------------
    const int tq = lane >> 2, tr = lane & 3;
    const int sub = lane >> 3, lr = lane & 7;
    float th[2][2], sr[2][2], cr[2][2];
    float om[2];
    int ig[2], bg[2], il[2], bl[2];
    #pragma unroll
    for (int half = 0; half < 2; half++) {
        il[half] = wm * 16 + half * 8 + tq;
        ig[half] = i0 + il[half];
        om[half] = omega[ig[half]];
    }
    #pragma unroll
    for (int nb = 0; nb < 2; nb++) {
        bl[nb] = wn * 8 + nb * 4 + tr;
        bg[nb] = nt * 16 + bl[nb];
    }

    const float kgn = Kg[0] * (1.0f / (float)NN);

    #pragma unroll
    for (int nb = 0; nb < 2; nb++)
        #pragma unroll
        for (int half = 0; half < 2; half++) {
            float tv = theta_init[bg[nb] * NN + ig[half]];
            th[nb][half] = tv;
            float s, c;
            sincosf(tv, &s, &c);
            sr[nb][half] = s;
            cr[nb][half] = c;
        }

    // publish step-0 B operand: stage fp8 in smem, then coalesced 16B stores
    __syncthreads();
    #pragma unroll
    for (int nb = 0; nb < 2; nb++)
        #pragma unroll
        for (int half = 0; half < 2; half++) {
            uint16_t pr;
            asm("cvt.rn.satfinite.e4m3x2.f32 %0, %1, %2;"
                : "=h"(pr) : "f"(cr[nb][half]), "f"(sr[nb][half]));
            sEp[(2 * bl[nb]) * 64 + il[half]]     = (uint8_t)(pr & 0xFF);
            sEp[(2 * bl[nb] + 1) * 64 + il[half]] = (uint8_t)(pr >> 8);
        }
    __syncthreads();
    if (t < 128) {
        int row = t >> 2, un = t & 3;
        *reinterpret_cast<uint4*>(&g_scB[0][(size_t)(n0 + row) * NN + i0 + un * 16]) =
            *reinterpret_cast<const uint4*>(sEp + row * 64 + un * 16);
    }

    group_bar(nt, gen);   // step-0 B operand published within group

    // ---------------- addressing ------------------------------------------
    const int arow = wm * 16 + ((sub & 1) << 3) + lr;
    const int acsel = sub >> 1;
    const int asw = (arow >> 1) & 3;
    const uint32_t aBase = sAu + (uint32_t)(arow * 64);

    const int brow = wn * 16 + ((sub >> 1) << 3) + lr;
    const int bcsel = sub & 1;
    const int bsw = (brow >> 1) & 3;
    const uint32_t bBase = sBu + (uint32_t)(brow * 64);

    // ---------------- 10 steps (unroll 1: keep registers sane) -------------
    #pragma unroll 1
    for (int s = 0; s < STEPS; s++) {
        const uint8_t* __restrict__ bsrc_t = g_scB[s & 1];
        uint8_t* __restrict__ Bdst = g_scB[(s + 1) & 1];

        float acc[2][2][4];   // [ks2][nb][frag]
        #pragma unroll
        for (int a2 = 0; a2 < 2; a2++)
            #pragma unroll
            for (int nb = 0; nb < 2; nb++)
                #pragma unroll
                for (int f = 0; f < 4; f++) acc[a2][nb][f] = 0.f;

        // issue whole 32KB fp8 B panel as 4 quarter-commits (8KB each)
        #pragma unroll
        for (int q = 0; q < 4; q++) {
            #pragma unroll
            for (int rep = 0; rep < 2; rep++) {
                int u = q * 512 + rep * 256 + t;
                int ck = u >> 7;
                int rem = u & 127;
                int row = rem >> 2;
                int un = rem & 3;
                uint32_t dst = sBu + (uint32_t)(ck * SB_STAGE + row * 64 +
                                                ((un ^ ((row >> 1) & 3)) << 4));
                cp16(dst, bsrc_t + (size_t)(n0 + row) * NN + ck * 64 + un * 16);
            }
            CP_COMMIT();
        }

        #define QUARTER(Q, WG)                                                          \
        {                                                                               \
            asm volatile("cp.async.wait_group " #WG ";" ::: "memory");                  \
            __syncthreads();                                                            \
            _Pragma("unroll")                                                           \
            for (int kk = (Q)*4; kk < (Q)*4 + 4; kk++) {                                \
                const uint32_t aC = aBase + (uint32_t)(kk * 4096);                      \
                const uint32_t bC = bBase + (uint32_t)(kk * SB_STAGE);                  \
                _Pragma("unroll")                                                       \
                for (int k2 = 0; k2 < 2; k2++) {                                        \
                    uint32_t a[4], b[4];                                                \
                    ldm4(a[0], a[1], a[2], a[3],                                        \
                         aC + (uint32_t)(((2 * k2 + acsel) ^ asw) << 4));               \
                    ldm4(b[0], b[1], b[2], b[3],                                        \
                         bC + (uint32_t)(((2 * k2 + bcsel) ^ bsw) << 4));               \
                    mma_fp8(acc[k2][0], a, b[0], b[1]);                                 \
                    mma_fp8(acc[k2][1], a, b[2], b[3]);                                 \
                }                                                                       \
            }                                                                           \
        }
        QUARTER(0, 3)
        QUARTER(1, 2)
        QUARTER(2, 1)
        QUARTER(3, 0)
        #undef QUARTER

        // fused Euler epilogue: MUFU sincos (abs err ~5e-7, << fp8 noise)
        __syncthreads();   // all warps done reading sB before staging overwrites it
        #pragma unroll
        for (int nb = 0; nb < 2; nb++) {
            #pragma unroll
            for (int half = 0; half < 2; half++) {
                float S = acc[0][nb][half * 2 + 0] + acc[1][nb][half * 2 + 0];
                float C = acc[0][nb][half * 2 + 1] + acc[1][nb][half * 2 + 1];
                float coup = cr[nb][half] * S - sr[nb][half] * C;
                float tn = th[nb][half] + DT * (om[half] + kgn * coup);
                th[nb][half] = tn;
                float sv = __sinf(tn);
                float cv = __cosf(tn);
                sr[nb][half] = sv;
                cr[nb][half] = cv;
                uint16_t pr;
                asm("cvt.rn.satfinite.e4m3x2.f32 %0, %1, %2;"
                    : "=h"(pr) : "f"(cv), "f"(sv));
                sEp[(2 * bl[nb]) * 64 + il[half]]     = (uint8_t)(pr & 0xFF);
                sEp[(2 * bl[nb] + 1) * 64 + il[half]] = (uint8_t)(pr >> 8);
            }
        }
        __syncthreads();
        if (t < 128) {
            int row = t >> 2, un = t & 3;
            *reinterpret_cast<uint4*>(&Bdst[(size_t)(n0 + row) * NN + i0 + un * 16]) =
                *reinterpret_cast<const uint4*>(sEp + row * 64 + un * 16);
        }
        if (s != STEPS - 1) group_bar(nt, gen);
    }

    // ---------------- finalize (group-local) --------------------------------
    float* redS = reinterpret_cast<float*>(smem + SA_BYTES + SB_BYTES);
    float* redC = redS + 16;
    __syncthreads();
    if (t < 16) { redS[t] = 0.f; redC[t] = 0.f; }
    __syncthreads();

    #pragma unroll
    for (int nb = 0; nb < 2; nb++) {
        atomicAdd(&redS[bl[nb]], sr[nb][0] + sr[nb][1]);
        atomicAdd(&redC[bl[nb]], cr[nb][0] + cr[nb][1]);
        #pragma unroll
        for (int half = 0; half < 2; half++)
            out[(size_t)bg[nb] * NN + ig[half]] = atan2f(sr[nb][half], cr[nb][half]);
    }
    __syncthreads();
    if (t < 16) {
        atomicAdd(&g_redS[nt * 16 + t], redS[t]);
        atomicAdd(&g_redC[nt * 16 + t], redC[t]);
    }
    group_bar(nt, gen);

    if (it == 0 && t < 16) {
        int b = nt * 16 + t;
        float sm = g_redS[b] * (1.0f / (float)NN);
        float cm = g_redC[b] * (1.0f / (float)NN);
        out[(size_t)BB * NN + b] = sqrtf(cm * cm + sm * sm);
    }
}

// ---------------------------------------------------------------------------
extern "C" void kernel_launch(void* const* d_in, const int* in_sizes, int n_in,
                              void* d_out, int out_size) {
    const float* theta_init = (const float*)d_in[0];
    const float* Kmat       = (const float*)d_in[1];
    const float* omega      = (const float*)d_in[2];
    const float* Kg         = (const float*)d_in[3];
    float* out = (float*)d_out;

    cudaFuncSetAttribute(kuramoto_kernel,
                         cudaFuncAttributeMaxDynamicSharedMemorySize, SM_TOTAL);
    zero_kernel<<<1, 128>>>();
    kuramoto_kernel<<<GRID, THREADS, SM_TOTAL>>>(theta_init, Kmat, omega, Kg, out);
}